// round 4
// baseline (speedup 1.0000x reference)
#include <cuda_runtime.h>

// SceneContraction, smem-staged, 512 samples/block, in-place results (2 syncs),
// streaming load/store hints. Stride loops (R3 had a truncated-unroll bug:
// C4/TPB and M4/TPB are not integers).
// means = contract(mean); cov_out = J cov J (J symmetric) for ||x||>=1, else pass.
// J = g*I + c*x x^T,  g=(2-1/m)/m,  c=2(1-m)/m^4,  m=||x||.

#define TPB     256
#define SPB     512                 // samples per block
#define M4      (SPB * 3 / 4)       // 384 float4 of mean per block
#define C4      (SPB * 9 / 4)       // 1152 float4 of cov per block

__device__ __forceinline__ void contract_one(
    float x0, float x1, float x2,
    float c00, float c01, float c02,
    float c10, float c11, float c12,
    float c20, float c21, float c22,
    float& r0, float& r1, float& r2,
    float& o00, float& o01, float& o02,
    float& o10, float& o11, float& o12,
    float& o20, float& o21, float& o22)
{
    float m2 = fmaf(x0, x0, fmaf(x1, x1, x2 * x2));
    float m  = sqrtf(m2);

    r0 = x0; r1 = x1; r2 = x2;
    o00 = c00; o01 = c01; o02 = c02;
    o10 = c10; o11 = c11; o12 = c12;
    o20 = c20; o21 = c21; o22 = c22;

    if (m >= 1.0f) {
        float inv  = 1.0f / m;
        float g    = (2.0f - inv) * inv;
        float inv2 = inv * inv;
        float cc   = 2.0f * (1.0f - m) * inv2 * inv2;

        r0 = g * x0; r1 = g * x1; r2 = g * x2;

        float J00 = fmaf(cc, x0 * x0, g);
        float J11 = fmaf(cc, x1 * x1, g);
        float J22 = fmaf(cc, x2 * x2, g);
        float J01 = cc * x0 * x1;
        float J02 = cc * x0 * x2;
        float J12 = cc * x1 * x2;

        float b00 = J00*c00 + J01*c10 + J02*c20;
        float b01 = J00*c01 + J01*c11 + J02*c21;
        float b02 = J00*c02 + J01*c12 + J02*c22;
        float b10 = J01*c00 + J11*c10 + J12*c20;
        float b11 = J01*c01 + J11*c11 + J12*c21;
        float b12 = J01*c02 + J11*c12 + J12*c22;
        float b20 = J02*c00 + J12*c10 + J22*c20;
        float b21 = J02*c01 + J12*c11 + J22*c21;
        float b22 = J02*c02 + J12*c12 + J22*c22;

        o00 = b00*J00 + b01*J01 + b02*J02;
        o01 = b00*J01 + b01*J11 + b02*J12;
        o02 = b00*J02 + b01*J12 + b02*J22;
        o10 = b10*J00 + b11*J01 + b12*J02;
        o11 = b10*J01 + b11*J11 + b12*J12;
        o12 = b10*J02 + b11*J12 + b12*J22;
        o20 = b20*J00 + b21*J01 + b22*J02;
        o21 = b20*J01 + b21*J11 + b22*J12;
        o22 = b20*J02 + b21*J12 + b22*J22;
    }
}

__global__ __launch_bounds__(TPB) void scene_contraction_kernel(
    const float* __restrict__ mean,   // [N,3]
    const float* __restrict__ cov,    // [N,3,3]
    float* __restrict__ out_mean,     // [N,3]
    float* __restrict__ out_cov,      // [N,3,3]
    int n)
{
    __shared__ float4 s_mean4[M4];
    __shared__ float4 s_cov4[C4];
    float* s_mean = reinterpret_cast<float*>(s_mean4);
    float* s_cov  = reinterpret_cast<float*>(s_cov4);

    const int t = threadIdx.x;
    const int base = blockIdx.x * SPB;

    if (base + SPB <= n) {
        // ---- coalesced streaming loads into smem (stride loops: exact coverage) ----
        const float4* gm = reinterpret_cast<const float4*>(mean) + (size_t)blockIdx.x * M4;
        const float4* gc = reinterpret_cast<const float4*>(cov)  + (size_t)blockIdx.x * C4;
        #pragma unroll
        for (int i = t; i < M4; i += TPB) s_mean4[i] = __ldcs(gm + i);
        #pragma unroll
        for (int i = t; i < C4; i += TPB) s_cov4[i] = __ldcs(gc + i);
        __syncthreads();

        // ---- compute 2 samples per thread, results written in place ----
        // Thread t owns samples t and t+TPB; only this thread reads/writes
        // their smem regions during compute, so no intermediate barrier.
        #pragma unroll
        for (int s = 0; s < SPB / TPB; s++) {
            const int idx = t + s * TPB;
            float x0 = s_mean[3*idx+0], x1 = s_mean[3*idx+1], x2 = s_mean[3*idx+2];
            float c00 = s_cov[9*idx+0], c01 = s_cov[9*idx+1], c02 = s_cov[9*idx+2];
            float c10 = s_cov[9*idx+3], c11 = s_cov[9*idx+4], c12 = s_cov[9*idx+5];
            float c20 = s_cov[9*idx+6], c21 = s_cov[9*idx+7], c22 = s_cov[9*idx+8];

            float r0, r1, r2, o00, o01, o02, o10, o11, o12, o20, o21, o22;
            contract_one(x0, x1, x2, c00, c01, c02, c10, c11, c12, c20, c21, c22,
                         r0, r1, r2, o00, o01, o02, o10, o11, o12, o20, o21, o22);

            s_mean[3*idx+0] = r0;  s_mean[3*idx+1] = r1;  s_mean[3*idx+2] = r2;
            s_cov[9*idx+0] = o00;  s_cov[9*idx+1] = o01;  s_cov[9*idx+2] = o02;
            s_cov[9*idx+3] = o10;  s_cov[9*idx+4] = o11;  s_cov[9*idx+5] = o12;
            s_cov[9*idx+6] = o20;  s_cov[9*idx+7] = o21;  s_cov[9*idx+8] = o22;
        }
        __syncthreads();

        // ---- coalesced streaming stores from smem ----
        float4* om = reinterpret_cast<float4*>(out_mean) + (size_t)blockIdx.x * M4;
        float4* oc = reinterpret_cast<float4*>(out_cov)  + (size_t)blockIdx.x * C4;
        #pragma unroll
        for (int i = t; i < M4; i += TPB) __stcs(om + i, s_mean4[i]);
        #pragma unroll
        for (int i = t; i < C4; i += TPB) __stcs(oc + i, s_cov4[i]);
    } else {
        // ---- scalar tail path ----
        for (int s = 0; s < SPB / TPB; s++) {
            int i = base + t + s * TPB;
            if (i >= n) return;
            const float* xp = mean + 3ull * i;
            const float* cp = cov + 9ull * i;
            float r0, r1, r2, o00, o01, o02, o10, o11, o12, o20, o21, o22;
            contract_one(xp[0], xp[1], xp[2],
                         cp[0], cp[1], cp[2], cp[3], cp[4], cp[5], cp[6], cp[7], cp[8],
                         r0, r1, r2, o00, o01, o02, o10, o11, o12, o20, o21, o22);
            float* om = out_mean + 3ull * i;
            float* oc = out_cov  + 9ull * i;
            om[0]=r0; om[1]=r1; om[2]=r2;
            oc[0]=o00; oc[1]=o01; oc[2]=o02;
            oc[3]=o10; oc[4]=o11; oc[5]=o12;
            oc[6]=o20; oc[7]=o21; oc[8]=o22;
        }
    }
}

extern "C" void kernel_launch(void* const* d_in, const int* in_sizes, int n_in,
                              void* d_out, int out_size)
{
    const float* mean = (const float*)d_in[0];   // [N,3]
    const float* cov  = (const float*)d_in[1];   // [N,3,3]
    int n = in_sizes[0] / 3;

    float* out_mean = (float*)d_out;
    float* out_cov  = (float*)d_out + 3ull * n;

    int blocks = (n + SPB - 1) / SPB;
    scene_contraction_kernel<<<blocks, TPB>>>(mean, cov, out_mean, out_cov, n);
}